// round 5
// baseline (speedup 1.0000x reference)
#include <cuda_runtime.h>

#define NPTS 4096
#define DIMS 1024
#define NCLS 64
#define EPSV 0.1f

#define RCH  32                 // row chunks for phase-1 partials
#define RPC  (NPTS / RCH)       // 128 rows per chunk
#define DCH  64                 // dims per phase-1 block
#define NDCH (DIMS / DCH)       // 16

// ---- static device scratch (no allocations allowed) ----
__device__ int    g_counts[NCLS];
__device__ float  g_spart[RCH][NCLS][DIMS];   // 8 MB partial class sums
__device__ float  g_Apart[RCH][DIMS];
__device__ float  g_Qpart[RCH][DIMS];
__device__ float  g_s[NCLS][DIMS];            // per-class, per-dim sums
__device__ float  g_w[DIMS];                  // weights
__device__ float  g_xw[(size_t)NPTS * DIMS];  // 16 MB: w ⊙ x
__device__ float  g_sq[NPTS];                 // sq_i = Σ_d w_d x_id²
__device__ float  g_P[NCLS];                  // Σ_{i∈k} sq_i
__device__ float  g_wss[NCLS];                // Σ_d w_d s_kd²
__device__ double g_pairsum;                  // Σ_{i<j} softplus(S_ij)

// ------------------------------------------------------------------
__global__ void k_zero() {
    int t = threadIdx.x;
    if (t < NCLS) { g_counts[t] = 0; g_P[t] = 0.f; }
    if (t == NCLS) g_pairsum = 0.0;
}

__global__ void k_count(const int* __restrict__ tgt) {
    int i = blockIdx.x * blockDim.x + threadIdx.x;
    if (i < NPTS) atomicAdd(&g_counts[tgt[i]], 1);
}

// Per (dim-chunk, row-chunk): partial class sums + Σ c_i x², Σ x²
__global__ void k_phase1(const float* __restrict__ X, const int* __restrict__ tgt) {
    __shared__ float s_sh[NCLS * DCH];   // 16 KB
    __shared__ float cnt_sh[NCLS];
    __shared__ int   tg_sh[RPC];
    int t  = threadIdx.x;                // 0..63
    int dc = blockIdx.x, rc = blockIdx.y;

    for (int i = t; i < NCLS * DCH; i += 64) s_sh[i] = 0.f;
    cnt_sh[t] = (float)g_counts[t];
    for (int r = t; r < RPC; r += 64) tg_sh[r] = tgt[rc * RPC + r];
    __syncthreads();

    const float* xp = X + (size_t)(rc * RPC) * DIMS + dc * DCH + t;
    float aacc = 0.f, qacc = 0.f;
    #pragma unroll 4
    for (int r = 0; r < RPC; r++) {
        float v = xp[(size_t)r * DIMS];
        int   k = tg_sh[r];
        s_sh[k * DCH + t] += v;
        float v2 = v * v;
        qacc += v2;
        aacc = fmaf(cnt_sh[k], v2, aacc);
    }
    __syncthreads();

    int d = dc * DCH + t;
    for (int k = 0; k < NCLS; k++)
        g_spart[rc][k][d] = s_sh[k * DCH + t];
    g_Apart[rc][d] = aacc;
    g_Qpart[rc][d] = qacc;
}

// Reduce partials, compute per-dim weight w_d
__global__ void k_weights() {
    int d = blockIdx.x * blockDim.x + threadIdx.x;   // 0..1023
    float sumc2 = 0.f;
    #pragma unroll
    for (int k = 0; k < NCLS; k++) { float c = (float)g_counts[k]; sumc2 += c * c; }
    float cntpos = sumc2 - (float)NPTS;
    float cntneg = (float)NPTS * (float)NPTS - sumc2;

    float ssum2 = 0.f, stot = 0.f;
    for (int k = 0; k < NCLS; k++) {
        float s = 0.f;
        #pragma unroll 8
        for (int rc = 0; rc < RCH; rc++) s += g_spart[rc][k][d];
        g_s[k][d] = s;
        ssum2 += s * s;
        stot  += s;
    }
    float A = 0.f, Q = 0.f;
    #pragma unroll 8
    for (int rc = 0; rc < RCH; rc++) { A += g_Apart[rc][d]; Q += g_Qpart[rc][d]; }

    float sum_pos = 2.f * A - 2.f * ssum2;
    float sum_neg = 2.f * (float)NPTS * Q - 2.f * A - 2.f * stot * stot + 2.f * ssum2;
    g_w[d] = cntneg / (sum_neg + EPSV) - cntpos / (sum_pos + EPSV);
}

// wss_k = Σ_d w_d s_kd²
__global__ void k_wss() {
    int k = blockIdx.x, t = threadIdx.x;
    float p = 0.f;
    for (int d = t; d < DIMS; d += 256) { float s = g_s[k][d]; p = fmaf(g_w[d] * s, s, p); }
    __shared__ float red[256];
    red[t] = p; __syncthreads();
    for (int off = 128; off > 0; off >>= 1) { if (t < off) red[t] += red[t + off]; __syncthreads(); }
    if (t == 0) g_wss[k] = red[0];
}

// xw = w ⊙ x ; sq_i = Σ w x² ; P_k += sq_i
__global__ void k_xwsq(const float* __restrict__ X, const int* __restrict__ tgt) {
    int i = blockIdx.x, t = threadIdx.x;   // 256 threads, 4 dims each
    const float4* xr = (const float4*)(X + (size_t)i * DIMS);
    const float4* wr = (const float4*)g_w;
    float4*       ow = (float4*)(g_xw + (size_t)i * DIMS);
    float4 x4 = xr[t], w4 = wr[t], o;
    o.x = x4.x * w4.x; o.y = x4.y * w4.y; o.z = x4.z * w4.z; o.w = x4.w * w4.w;
    ow[t] = o;
    float acc = x4.x * o.x + x4.y * o.y + x4.z * o.z + x4.w * o.w;
    __shared__ float red[256];
    red[t] = acc; __syncthreads();
    for (int off = 128; off > 0; off >>= 1) { if (t < off) red[t] += red[t + off]; __syncthreads(); }
    if (t == 0) { g_sq[i] = red[0]; atomicAdd(&g_P[tgt[i]], red[0]); }
}

// Fused triangular Gram + softplus reduction.
// Block (bi,bj), bi<=bj, computes G tile of X[bi-rows] · xw[bj-rows]^T,
// forms S = sq_i + sq_j - 2G, accumulates softplus(S) over valid pairs.
__global__ void __launch_bounds__(256) k_main(const float* __restrict__ X) {
    int bj = blockIdx.x, bi = blockIdx.y;
    if (bi > bj) return;

    __shared__ float As[8][128];
    __shared__ float Bs[8][128];
    __shared__ float red[256];

    int tid = threadIdx.x;
    int tx = tid & 15, ty = tid >> 4;
    int iBase = bi * 128, jBase = bj * 128;

    int lRow = tid >> 1;            // 0..127
    int lCol = (tid & 1) * 4;       // 0 or 4
    const float* Ap = X    + (size_t)(iBase + lRow) * DIMS + lCol;
    const float* Bp = g_xw + (size_t)(jBase + lRow) * DIMS + lCol;

    float acc[8][8];
    #pragma unroll
    for (int m = 0; m < 8; m++)
        #pragma unroll
        for (int n = 0; n < 8; n++) acc[m][n] = 0.f;

    for (int k0 = 0; k0 < DIMS; k0 += 8) {
        float4 av = *(const float4*)(Ap + k0);
        float4 bv = *(const float4*)(Bp + k0);
        __syncthreads();
        As[lCol + 0][lRow] = av.x; As[lCol + 1][lRow] = av.y;
        As[lCol + 2][lRow] = av.z; As[lCol + 3][lRow] = av.w;
        Bs[lCol + 0][lRow] = bv.x; Bs[lCol + 1][lRow] = bv.y;
        Bs[lCol + 2][lRow] = bv.z; Bs[lCol + 3][lRow] = bv.w;
        __syncthreads();
        #pragma unroll
        for (int kk = 0; kk < 8; kk++) {
            float a[8], b[8];
            #pragma unroll
            for (int m = 0; m < 8; m++) a[m] = As[kk][ty * 8 + m];
            #pragma unroll
            for (int n = 0; n < 8; n++) b[n] = Bs[kk][tx * 8 + n];
            #pragma unroll
            for (int m = 0; m < 8; m++)
                #pragma unroll
                for (int n = 0; n < 8; n++)
                    acc[m][n] = fmaf(a[m], b[n], acc[m][n]);
        }
    }

    float sqi[8], sqj[8];
    #pragma unroll
    for (int m = 0; m < 8; m++) sqi[m] = g_sq[iBase + ty * 8 + m];
    #pragma unroll
    for (int n = 0; n < 8; n++) sqj[n] = g_sq[jBase + tx * 8 + n];

    float lsum = 0.f;
    bool diag = (bi == bj);
    #pragma unroll
    for (int m = 0; m < 8; m++) {
        int gi = iBase + ty * 8 + m;
        #pragma unroll
        for (int n = 0; n < 8; n++) {
            int gj = jBase + tx * 8 + n;
            if (!diag || gi < gj) {
                float S = sqi[m] + sqj[n] - 2.f * acc[m][n];
                lsum += fmaxf(S, 0.f) + log1pf(expf(-fabsf(S)));
            }
        }
    }

    red[tid] = lsum; __syncthreads();
    for (int off = 128; off > 0; off >>= 1) { if (tid < off) red[tid] += red[tid + off]; __syncthreads(); }
    if (tid == 0) atomicAdd(&g_pairsum, (double)red[0]);
}

// loss = (2·pairsum − Σ_k (2 c_k P_k − 2 wss_k)) / (N(N−1))
__global__ void k_final(float* __restrict__ out) {
    __shared__ float red[NCLS];
    int t = threadIdx.x;
    float c = (float)g_counts[t];
    red[t] = 2.f * c * g_P[t] - 2.f * g_wss[t];
    __syncthreads();
    if (t == 0) {
        double ts = 0.0;
        for (int k = 0; k < NCLS; k++) ts += (double)red[k];
        double denom = (double)NPTS * (double)(NPTS - 1);
        out[0] = (float)((2.0 * g_pairsum - ts) / denom);
    }
}

// ------------------------------------------------------------------
extern "C" void kernel_launch(void* const* d_in, const int* in_sizes, int n_in,
                              void* d_out, int out_size) {
    const float* X   = (const float*)d_in[0];
    const int*   tgt = (const int*)d_in[1];
    float*       out = (float*)d_out;
    (void)in_sizes; (void)n_in; (void)out_size;

    k_zero<<<1, 128>>>();
    k_count<<<NPTS / 256, 256>>>(tgt);
    k_phase1<<<dim3(NDCH, RCH), 64>>>(X, tgt);
    k_weights<<<DIMS / 256, 256>>>();
    k_wss<<<NCLS, 256>>>();
    k_xwsq<<<NPTS, 256>>>(X, tgt);
    k_main<<<dim3(NPTS / 128, NPTS / 128), 256>>>(X);
    k_final<<<1, NCLS>>>(out);
}

// round 6
// speedup vs baseline: 2.4577x; 2.4577x over previous
#include <cuda_runtime.h>
#include <cstdint>

#define NPTS 4096
#define DIMS 1024
#define NCLS 64
#define EPSV 0.1f

#define RCH  32                 // row chunks for phase-1 partials
#define RPC  (NPTS / RCH)       // 128 rows per chunk
#define DCH  64                 // dims per phase-1 block
#define NDCH (DIMS / DCH)       // 16

// ---- static device scratch (no allocations allowed) ----
__device__ int    g_counts[NCLS];
__device__ float  g_spart[RCH][DIMS][NCLS];   // 8 MB partial class sums (class-contig!)
__device__ float  g_Apart[RCH][DIMS];
__device__ float  g_Qpart[RCH][DIMS];
__device__ float  g_s[NCLS][DIMS];            // per-class, per-dim sums
__device__ float  g_w[DIMS];                  // weights
__device__ float  g_xw[(size_t)NPTS * DIMS];  // 16 MB: w ⊙ x
__device__ float  g_sq[NPTS];                 // sq_i = Σ_d w_d x_id²
__device__ float  g_P[NCLS];                  // Σ_{i∈k} sq_i
__device__ float  g_wss[NCLS];                // Σ_d w_d s_kd²
__device__ double g_pairsum;                  // Σ_{i<j} softplus(S_ij)

__device__ __forceinline__ uint32_t f2tf(float x) {
    uint32_t r; asm("cvt.rna.tf32.f32 %0, %1;" : "=r"(r) : "f"(x)); return r;
}

// ------------------------------------------------------------------
__global__ void k_zero() {
    int t = threadIdx.x;
    if (t < NCLS) { g_counts[t] = 0; g_P[t] = 0.f; }
    if (t == NCLS) g_pairsum = 0.0;
}

__global__ void k_count(const int* __restrict__ tgt) {
    int i = blockIdx.x * blockDim.x + threadIdx.x;
    if (i < NPTS) atomicAdd(&g_counts[tgt[i]], 1);
}

// Per (dim-chunk, row-chunk): partial class sums + Σ c_i x², Σ x²
__global__ void k_phase1(const float* __restrict__ X, const int* __restrict__ tgt) {
    __shared__ float s_sh[NCLS * DCH];   // 16 KB
    __shared__ float cnt_sh[NCLS];
    __shared__ int   tg_sh[RPC];
    int t  = threadIdx.x;                // 0..63
    int dc = blockIdx.x, rc = blockIdx.y;

    for (int i = t; i < NCLS * DCH; i += 64) s_sh[i] = 0.f;
    cnt_sh[t] = (float)g_counts[t];
    for (int r = t; r < RPC; r += 64) tg_sh[r] = tgt[rc * RPC + r];
    __syncthreads();

    const float* xp = X + (size_t)(rc * RPC) * DIMS + dc * DCH + t;
    float aacc = 0.f, qacc = 0.f;
    #pragma unroll 4
    for (int r = 0; r < RPC; r++) {
        float v = xp[(size_t)r * DIMS];
        int   k = tg_sh[r];
        s_sh[k * DCH + t] += v;
        float v2 = v * v;
        qacc += v2;
        aacc = fmaf(cnt_sh[k], v2, aacc);
    }
    __syncthreads();

    int d = dc * DCH + t;
    #pragma unroll
    for (int k4 = 0; k4 < NCLS; k4 += 4) {
        float4 v = make_float4(s_sh[(k4 + 0) * DCH + t], s_sh[(k4 + 1) * DCH + t],
                               s_sh[(k4 + 2) * DCH + t], s_sh[(k4 + 3) * DCH + t]);
        *(float4*)&g_spart[rc][d][k4] = v;
    }
    g_Apart[rc][d] = aacc;
    g_Qpart[rc][d] = qacc;
}

// Parallel per-dim reduction of partials + weight computation.
// One block per dim (1024 blocks), 64 threads (one per class): coalesced 256B rows.
__global__ void k_reduce_w() {
    int d = blockIdx.x, k = threadIdx.x;
    float s = 0.f;
    #pragma unroll 8
    for (int rc = 0; rc < RCH; rc++) s += g_spart[rc][d][k];
    g_s[k][d] = s;
    float c = (float)g_counts[k];

    __shared__ float sh1[NCLS], sh2[NCLS], sh3[NCLS];
    sh1[k] = s * s; sh2[k] = s; sh3[k] = c * c;
    __syncthreads();
    for (int off = 32; off > 0; off >>= 1) {
        if (k < off) { sh1[k] += sh1[k + off]; sh2[k] += sh2[k + off]; sh3[k] += sh3[k + off]; }
        __syncthreads();
    }

    if (k < 32) {                       // warp 0: reduce A, Q over rc
        float a = g_Apart[k][d];
        float q = g_Qpart[k][d];
        #pragma unroll
        for (int off = 16; off > 0; off >>= 1) {
            a += __shfl_down_sync(0xffffffffu, a, off);
            q += __shfl_down_sync(0xffffffffu, q, off);
        }
        if (k == 0) {
            float ssum2 = sh1[0], stot = sh2[0], sumc2 = sh3[0];
            float cntpos = sumc2 - (float)NPTS;
            float cntneg = (float)NPTS * (float)NPTS - sumc2;
            float sum_pos = 2.f * a - 2.f * ssum2;
            float sum_neg = 2.f * (float)NPTS * q - 2.f * a - 2.f * stot * stot + 2.f * ssum2;
            g_w[d] = cntneg / (sum_neg + EPSV) - cntpos / (sum_pos + EPSV);
        }
    }
}

// wss_k = Σ_d w_d s_kd²
__global__ void k_wss() {
    int k = blockIdx.x, t = threadIdx.x;
    float p = 0.f;
    for (int d = t; d < DIMS; d += 256) { float s = g_s[k][d]; p = fmaf(g_w[d] * s, s, p); }
    __shared__ float red[256];
    red[t] = p; __syncthreads();
    for (int off = 128; off > 0; off >>= 1) { if (t < off) red[t] += red[t + off]; __syncthreads(); }
    if (t == 0) g_wss[k] = red[0];
}

// xw = w ⊙ x ; sq_i = Σ w x² ; P_k += sq_i
__global__ void k_xwsq(const float* __restrict__ X, const int* __restrict__ tgt) {
    int i = blockIdx.x, t = threadIdx.x;   // 256 threads, 4 dims each
    const float4* xr = (const float4*)(X + (size_t)i * DIMS);
    const float4* wr = (const float4*)g_w;
    float4*       ow = (float4*)(g_xw + (size_t)i * DIMS);
    float4 x4 = xr[t], w4 = wr[t], o;
    o.x = x4.x * w4.x; o.y = x4.y * w4.y; o.z = x4.z * w4.z; o.w = x4.w * w4.w;
    ow[t] = o;
    float acc = x4.x * o.x + x4.y * o.y + x4.z * o.z + x4.w * o.w;
    __shared__ float red[256];
    red[t] = acc; __syncthreads();
    for (int off = 128; off > 0; off >>= 1) { if (t < off) red[t] += red[t + off]; __syncthreads(); }
    if (t == 0) { g_sq[i] = red[0]; atomicAdd(&g_P[tgt[i]], red[0]); }
}

// ------------------------------------------------------------------
// tf32 tensor-core fused Gram + softplus reduction.
// Block tile 256(m) x 128(n), BK=16, 8 warps each computing 64x64 via
// mma.sync.m16n8k8 (4 m-frags x 8 n-frags). smem stride 20 floats ->
// fragment-load bank index = 4r + c : conflict-free.
#define BMM 256
#define BNN 128
#define BKK 16
#define LSTR 20

__global__ void __launch_bounds__(256) k_main(const float* __restrict__ X) {
    int bj = blockIdx.x;                 // 0..31 (cols of 128)
    int bi = blockIdx.y;                 // 0..15 (rows of 256)
    if (bj * BNN + BNN <= bi * BMM) return;   // fully below diagonal
    int iBase = bi * BMM, jBase = bj * BNN;

    __shared__ uint32_t As[BMM * LSTR];  // 20 KB
    __shared__ uint32_t Bs[BNN * LSTR];  // 10 KB
    __shared__ float    red[256];

    int t = threadIdx.x;
    int lane = t & 31, w = t >> 5;
    int warpRow = w & 3, warpCol = w >> 2;   // 4 x 2 warp grid

    float acc[4][8][4];
    #pragma unroll
    for (int mf = 0; mf < 4; mf++)
        #pragma unroll
        for (int nf = 0; nf < 8; nf++)
            #pragma unroll
            for (int q = 0; q < 4; q++) acc[mf][nf][q] = 0.f;

    const float* Abase = X    + (size_t)iBase * DIMS;
    const float* Bbase = g_xw + (size_t)jBase * DIMS;
    int am = t >> 2;                 // base row (+64p)
    int ak = (t & 3) * 4;            // k offset within tile

    for (int kt = 0; kt < DIMS; kt += BKK) {
        __syncthreads();
        #pragma unroll
        for (int p = 0; p < 4; p++) {        // A: 256 rows
            int m = am + 64 * p;
            float4 v = *(const float4*)(Abase + (size_t)m * DIMS + kt + ak);
            uint4 u = make_uint4(f2tf(v.x), f2tf(v.y), f2tf(v.z), f2tf(v.w));
            *(uint4*)&As[m * LSTR + ak] = u;
        }
        #pragma unroll
        for (int p = 0; p < 2; p++) {        // B: 128 rows
            int m = am + 64 * p;
            float4 v = *(const float4*)(Bbase + (size_t)m * DIMS + kt + ak);
            uint4 u = make_uint4(f2tf(v.x), f2tf(v.y), f2tf(v.z), f2tf(v.w));
            *(uint4*)&Bs[m * LSTR + ak] = u;
        }
        __syncthreads();

        #pragma unroll
        for (int kk = 0; kk < BKK; kk += 8) {
            uint32_t bf[8][2];
            #pragma unroll
            for (int nf = 0; nf < 8; nf++) {
                int n = warpCol * 64 + nf * 8 + (lane >> 2);
                bf[nf][0] = Bs[n * LSTR + kk + (lane & 3)];
                bf[nf][1] = Bs[n * LSTR + kk + (lane & 3) + 4];
            }
            #pragma unroll
            for (int mf = 0; mf < 4; mf++) {
                int m = warpRow * 64 + mf * 16 + (lane >> 2);
                uint32_t a0 = As[m * LSTR + kk + (lane & 3)];
                uint32_t a1 = As[(m + 8) * LSTR + kk + (lane & 3)];
                uint32_t a2 = As[m * LSTR + kk + (lane & 3) + 4];
                uint32_t a3 = As[(m + 8) * LSTR + kk + (lane & 3) + 4];
                #pragma unroll
                for (int nf = 0; nf < 8; nf++) {
                    asm volatile(
                        "mma.sync.aligned.m16n8k8.row.col.f32.tf32.tf32.f32 "
                        "{%0,%1,%2,%3}, {%4,%5,%6,%7}, {%8,%9}, {%0,%1,%2,%3};"
                        : "+f"(acc[mf][nf][0]), "+f"(acc[mf][nf][1]),
                          "+f"(acc[mf][nf][2]), "+f"(acc[mf][nf][3])
                        : "r"(a0), "r"(a1), "r"(a2), "r"(a3),
                          "r"(bf[nf][0]), "r"(bf[nf][1]));
                }
            }
        }
    }

    // Epilogue: S = sq_i + sq_j - 2G, softplus over strict upper triangle.
    int g = lane >> 2, tg = lane & 3;
    float sqj[8][2];
    int jc[8];
    #pragma unroll
    for (int nf = 0; nf < 8; nf++) {
        int j0 = jBase + warpCol * 64 + nf * 8 + 2 * tg;
        jc[nf] = j0;
        sqj[nf][0] = g_sq[j0];
        sqj[nf][1] = g_sq[j0 + 1];
    }

    float lsum = 0.f;
    #pragma unroll
    for (int mf = 0; mf < 4; mf++) {
        int i0 = iBase + warpRow * 64 + mf * 16 + g;
        float sqi0 = g_sq[i0], sqi1 = g_sq[i0 + 8];
        #pragma unroll
        for (int nf = 0; nf < 8; nf++) {
            int j0 = jc[nf];
            float S;
            if (i0 < j0) {
                S = sqi0 + sqj[nf][0] - 2.f * acc[mf][nf][0];
                lsum += fmaxf(S, 0.f) + log1pf(expf(-fabsf(S)));
            }
            if (i0 < j0 + 1) {
                S = sqi0 + sqj[nf][1] - 2.f * acc[mf][nf][1];
                lsum += fmaxf(S, 0.f) + log1pf(expf(-fabsf(S)));
            }
            if (i0 + 8 < j0) {
                S = sqi1 + sqj[nf][0] - 2.f * acc[mf][nf][2];
                lsum += fmaxf(S, 0.f) + log1pf(expf(-fabsf(S)));
            }
            if (i0 + 8 < j0 + 1) {
                S = sqi1 + sqj[nf][1] - 2.f * acc[mf][nf][3];
                lsum += fmaxf(S, 0.f) + log1pf(expf(-fabsf(S)));
            }
        }
    }

    red[t] = lsum; __syncthreads();
    for (int off = 128; off > 0; off >>= 1) { if (t < off) red[t] += red[t + off]; __syncthreads(); }
    if (t == 0) atomicAdd(&g_pairsum, (double)red[0]);
}

// loss = (2·pairsum − Σ_k (2 c_k P_k − 2 wss_k)) / (N(N−1))
__global__ void k_final(float* __restrict__ out) {
    __shared__ float red[NCLS];
    int t = threadIdx.x;
    float c = (float)g_counts[t];
    red[t] = 2.f * c * g_P[t] - 2.f * g_wss[t];
    __syncthreads();
    if (t == 0) {
        double ts = 0.0;
        for (int k = 0; k < NCLS; k++) ts += (double)red[k];
        double denom = (double)NPTS * (double)(NPTS - 1);
        out[0] = (float)((2.0 * g_pairsum - ts) / denom);
    }
}

// ------------------------------------------------------------------
extern "C" void kernel_launch(void* const* d_in, const int* in_sizes, int n_in,
                              void* d_out, int out_size) {
    const float* X   = (const float*)d_in[0];
    const int*   tgt = (const int*)d_in[1];
    float*       out = (float*)d_out;
    (void)in_sizes; (void)n_in; (void)out_size;

    k_zero<<<1, 128>>>();
    k_count<<<NPTS / 256, 256>>>(tgt);
    k_phase1<<<dim3(NDCH, RCH), 64>>>(X, tgt);
    k_reduce_w<<<DIMS, NCLS>>>();
    k_wss<<<NCLS, 256>>>();
    k_xwsq<<<NPTS, 256>>>(X, tgt);
    k_main<<<dim3(NPTS / BNN, NPTS / BMM), 256>>>(X);
    k_final<<<1, NCLS>>>(out);
}

// round 8
// speedup vs baseline: 4.3844x; 1.7840x over previous
#include <cuda_runtime.h>
#include <cuda_bf16.h>
#include <cstdint>

#define NPTS 4096
#define DIMS 1024
#define NCLS 64
#define EPSV 0.1f

#define RCH  16                 // row chunks for phase-1 partials
#define RPC  (NPTS / RCH)       // 256 rows per chunk
#define DCH  64                 // dims per phase-1 block
#define NDCH (DIMS / DCH)       // 16

// k_main tiling (bf16 mma.sync m16n8k16)
#define BM   256
#define BN   128
#define BK   32                 // bf16 elems per chunk
#define NCH  (DIMS / BK)        // 32 chunks
#define NTILES 272              // triangle tiles: sum_{bi<16} (32 - 2*bi)
#define LSTRH 40                // smem row stride in halfs (80 B)
#define A_HALFS (BM * LSTRH)    // 10240 halfs = 20480 B
#define B_HALFS (BN * LSTRH)    //  5120 halfs = 10240 B
#define STGB  ((A_HALFS + B_HALFS) * 2)   // 30720 B per stage
#define NSTG  3
#define DSMEM_BYTES (NSTG * STGB)         // 92160 B

// ---- static device scratch (no allocations allowed) ----
__device__ int      g_counts[NCLS];
__device__ float    g_spart[RCH][DIMS][NCLS];   // 4 MB partial class sums
__device__ float    g_Apart[RCH][DIMS];
__device__ float    g_Qpart[RCH][DIMS];
__device__ float    g_s[NCLS][DIMS];
__device__ float    g_w[DIMS];
__device__ unsigned short g_xh[(size_t)NPTS * DIMS];   // bf16(x)
__device__ unsigned short g_xwh[(size_t)NPTS * DIMS];  // bf16(w*x)
__device__ float    g_sq[NPTS];                 // sq_i = sum_d w_d x_id^2 (fp32 exact)
__device__ float    g_P[NCLS];
__device__ float    g_wss[NCLS];
__device__ double   g_pairsum;

// ---------------- helpers ----------------
__device__ __forceinline__ uint32_t smem_u32(const void* p) {
    uint32_t a;
    asm("{ .reg .u64 t; cvta.to.shared.u64 t, %1; cvt.u32.u64 %0, t; }" : "=r"(a) : "l"(p));
    return a;
}
__device__ __forceinline__ void cp16(uint32_t dst, const void* src) {
    asm volatile("cp.async.cg.shared.global [%0], [%1], 16;" :: "r"(dst), "l"(src) : "memory");
}
__device__ __forceinline__ void ldm_x4(uint32_t& r0, uint32_t& r1, uint32_t& r2, uint32_t& r3,
                                       uint32_t addr) {
    asm volatile("ldmatrix.sync.aligned.m8n8.x4.shared.b16 {%0,%1,%2,%3}, [%4];"
                 : "=r"(r0), "=r"(r1), "=r"(r2), "=r"(r3) : "r"(addr));
}
__device__ __forceinline__ void mma_bf16(float* c, uint32_t a0, uint32_t a1, uint32_t a2,
                                         uint32_t a3, uint32_t b0, uint32_t b1) {
    asm volatile("mma.sync.aligned.m16n8k16.row.col.f32.bf16.bf16.f32 "
                 "{%0,%1,%2,%3}, {%4,%5,%6,%7}, {%8,%9}, {%0,%1,%2,%3};"
                 : "+f"(c[0]), "+f"(c[1]), "+f"(c[2]), "+f"(c[3])
                 : "r"(a0), "r"(a1), "r"(a2), "r"(a3), "r"(b0), "r"(b1));
}

// ------------------------------------------------------------------
__global__ void k_zero() {
    int t = threadIdx.x;
    if (t < NCLS) { g_counts[t] = 0; g_P[t] = 0.f; }
    if (t == NCLS) g_pairsum = 0.0;
}

__global__ void k_count(const int* __restrict__ tgt) {
    int i = blockIdx.x * blockDim.x + threadIdx.x;
    if (i < NPTS) atomicAdd(&g_counts[tgt[i]], 1);
}

__global__ void k_phase1(const float* __restrict__ X, const int* __restrict__ tgt) {
    __shared__ float s_sh[NCLS * DCH];
    __shared__ float cnt_sh[NCLS];
    __shared__ int   tg_sh[RPC];
    int t  = threadIdx.x;                // 0..63
    int dc = blockIdx.x, rc = blockIdx.y;

    for (int i = t; i < NCLS * DCH; i += 64) s_sh[i] = 0.f;
    cnt_sh[t] = (float)g_counts[t];
    for (int r = t; r < RPC; r += 64) tg_sh[r] = tgt[rc * RPC + r];
    __syncthreads();

    const float* xp = X + (size_t)(rc * RPC) * DIMS + dc * DCH + t;
    float aacc = 0.f, qacc = 0.f;
    #pragma unroll 4
    for (int r = 0; r < RPC; r++) {
        float v = xp[(size_t)r * DIMS];
        int   k = tg_sh[r];
        s_sh[k * DCH + t] += v;
        float v2 = v * v;
        qacc += v2;
        aacc = fmaf(cnt_sh[k], v2, aacc);
    }
    __syncthreads();

    int d = dc * DCH + t;
    #pragma unroll
    for (int k4 = 0; k4 < NCLS; k4 += 4) {
        float4 v = make_float4(s_sh[(k4 + 0) * DCH + t], s_sh[(k4 + 1) * DCH + t],
                               s_sh[(k4 + 2) * DCH + t], s_sh[(k4 + 3) * DCH + t]);
        *(float4*)&g_spart[rc][d][k4] = v;
    }
    g_Apart[rc][d] = aacc;
    g_Qpart[rc][d] = qacc;
}

__global__ void k_reduce_w() {
    int d = blockIdx.x, k = threadIdx.x;
    float s = 0.f;
    #pragma unroll
    for (int rc = 0; rc < RCH; rc++) s += g_spart[rc][d][k];
    g_s[k][d] = s;
    float c = (float)g_counts[k];

    __shared__ float sh1[NCLS], sh2[NCLS], sh3[NCLS];
    sh1[k] = s * s; sh2[k] = s; sh3[k] = c * c;
    __syncthreads();
    for (int off = 32; off > 0; off >>= 1) {
        if (k < off) { sh1[k] += sh1[k + off]; sh2[k] += sh2[k + off]; sh3[k] += sh3[k + off]; }
        __syncthreads();
    }

    if (k < RCH) {
        float a = g_Apart[k][d];
        float q = g_Qpart[k][d];
        #pragma unroll
        for (int off = RCH / 2; off > 0; off >>= 1) {
            a += __shfl_down_sync(0xffffffffu, a, off);
            q += __shfl_down_sync(0xffffffffu, q, off);
        }
        if (k == 0) {
            float ssum2 = sh1[0], stot = sh2[0], sumc2 = sh3[0];
            float cntpos = sumc2 - (float)NPTS;
            float cntneg = (float)NPTS * (float)NPTS - sumc2;
            float sum_pos = 2.f * a - 2.f * ssum2;
            float sum_neg = 2.f * (float)NPTS * q - 2.f * a - 2.f * stot * stot + 2.f * ssum2;
            g_w[d] = cntneg / (sum_neg + EPSV) - cntpos / (sum_pos + EPSV);
        }
    }
}

__global__ void k_wss() {
    int k = blockIdx.x, t = threadIdx.x;
    float p = 0.f;
    for (int d = t; d < DIMS; d += 256) { float s = g_s[k][d]; p = fmaf(g_w[d] * s, s, p); }
    __shared__ float red[256];
    red[t] = p; __syncthreads();
    for (int off = 128; off > 0; off >>= 1) { if (t < off) red[t] += red[t + off]; __syncthreads(); }
    if (t == 0) g_wss[k] = red[0];
}

// xh = bf16(x), xwh = bf16(w*x), sq_i = sum w x^2 (fp32), P_k += sq_i
__global__ void k_xwsq(const float* __restrict__ X, const int* __restrict__ tgt) {
    int i = blockIdx.x, t = threadIdx.x;   // 256 threads, 4 dims each
    const float4* xr = (const float4*)(X + (size_t)i * DIMS);
    const float4* wr = (const float4*)g_w;
    float4 x4 = xr[t], w4 = wr[t], o;
    o.x = x4.x * w4.x; o.y = x4.y * w4.y; o.z = x4.z * w4.z; o.w = x4.w * w4.w;
    float acc = x4.x * o.x + x4.y * o.y + x4.z * o.z + x4.w * o.w;

    __nv_bfloat162 hx0 = __floats2bfloat162_rn(x4.x, x4.y);
    __nv_bfloat162 hx1 = __floats2bfloat162_rn(x4.z, x4.w);
    __nv_bfloat162 ho0 = __floats2bfloat162_rn(o.x, o.y);
    __nv_bfloat162 ho1 = __floats2bfloat162_rn(o.z, o.w);
    uint2* dxh  = (uint2*)(g_xh  + (size_t)i * DIMS);
    uint2* dxwh = (uint2*)(g_xwh + (size_t)i * DIMS);
    uint2 px, po;
    px.x = *(uint32_t*)&hx0; px.y = *(uint32_t*)&hx1;
    po.x = *(uint32_t*)&ho0; po.y = *(uint32_t*)&ho1;
    dxh[t] = px; dxwh[t] = po;

    __shared__ float red[256];
    red[t] = acc; __syncthreads();
    for (int off = 128; off > 0; off >>= 1) { if (t < off) red[t] += red[t + off]; __syncthreads(); }
    if (t == 0) { g_sq[i] = red[0]; atomicAdd(&g_P[tgt[i]], red[0]); }
}

// ------------------------------------------------------------------
// bf16 mma.sync fused Gram + softplus. 256x128 tile, BK=32, 3-stage cp.async,
// ldmatrix.x4 fragments, 8 warps (4m x 2n) each 64x64.
__device__ __forceinline__ void load_stage(uint32_t sA, uint32_t sB,
                                           const unsigned short* Ag,
                                           const unsigned short* Bg,
                                           int kt, int t) {
    int seg = t & 3;               // 16B segment within row (8 halfs)
    int r0  = t >> 2;              // 64 rows per pass
    #pragma unroll
    for (int p = 0; p < 4; p++) {  // A: 256 rows
        int row = r0 + 64 * p;
        cp16(sA + row * 80u + seg * 16u, Ag + (size_t)row * DIMS + kt + seg * 8);
    }
    #pragma unroll
    for (int p = 0; p < 2; p++) {  // B: 128 rows
        int row = r0 + 64 * p;
        cp16(sB + row * 80u + seg * 16u, Bg + (size_t)row * DIMS + kt + seg * 8);
    }
    asm volatile("cp.async.commit_group;" ::: "memory");
}

__global__ void __launch_bounds__(256) k_main() {
    // map linear block id -> (bi, bj) on the triangle bj >= 2*bi
    int L = blockIdx.x, bi = 0, cnt = 32;
    while (L >= cnt) { L -= cnt; bi++; cnt -= 2; }
    int bj = 2 * bi + L;
    int iBase = bi * BM, jBase = bj * BN;

    extern __shared__ char dsmem[];
    __shared__ float red[256];

    int t = threadIdx.x;
    int lane = t & 31, w = t >> 5;
    int warpRow = w & 3, warpCol = w >> 2;    // 4 x 2 warps
    uint32_t sbase = smem_u32(dsmem);

    const unsigned short* Ag = g_xh  + (size_t)iBase * DIMS;
    const unsigned short* Bg = g_xwh + (size_t)jBase * DIMS;

    float acc[4][8][4];
    #pragma unroll
    for (int mf = 0; mf < 4; mf++)
        #pragma unroll
        for (int nf = 0; nf < 8; nf++)
            #pragma unroll
            for (int q = 0; q < 4; q++) acc[mf][nf][q] = 0.f;

    // prologue: chunks 0 and 1 into stages 0 and 1
    load_stage(sbase,        sbase + A_HALFS * 2,        Ag, Bg, 0,  t);
    load_stage(sbase + STGB, sbase + STGB + A_HALFS * 2, Ag, Bg, BK, t);

    // precomputed fragment address components
    uint32_t aRow = (uint32_t)(warpRow * 64 + (lane & 15));
    uint32_t aKof = (uint32_t)((lane >> 4) * 16);
    int grp = lane >> 3;
    uint32_t bRowB = (uint32_t)(warpCol * 64 + ((grp >> 1) << 3) + (lane & 7));
    uint32_t bKof = (uint32_t)((grp & 1) * 16);

    for (int c = 0; c < NCH; c++) {
        uint32_t sA = sbase + (uint32_t)(c % NSTG) * STGB;
        uint32_t sB = sA + A_HALFS * 2;
        if (c + 2 < NCH) asm volatile("cp.async.wait_group 1;" ::: "memory");
        else             asm volatile("cp.async.wait_group 0;" ::: "memory");
        __syncthreads();

        if (c + 2 < NCH)
            load_stage(sbase + (uint32_t)((c + 2) % NSTG) * STGB,
                       sbase + (uint32_t)((c + 2) % NSTG) * STGB + A_HALFS * 2,
                       Ag, Bg, (c + 2) * BK, t);

        #pragma unroll
        for (int ks = 0; ks < 2; ks++) {
            uint32_t a[4][4], b[8][2];
            #pragma unroll
            for (int nfp = 0; nfp < 4; nfp++) {
                uint32_t addr = sB + (bRowB + nfp * 16) * 80u + ks * 32u + bKof;
                ldm_x4(b[2 * nfp][0], b[2 * nfp][1], b[2 * nfp + 1][0], b[2 * nfp + 1][1], addr);
            }
            #pragma unroll
            for (int mf = 0; mf < 4; mf++) {
                uint32_t addr = sA + (aRow + mf * 16) * 80u + ks * 32u + aKof;
                ldm_x4(a[mf][0], a[mf][1], a[mf][2], a[mf][3], addr);
            }
            #pragma unroll
            for (int mf = 0; mf < 4; mf++)
                #pragma unroll
                for (int nf = 0; nf < 8; nf++)
                    mma_bf16(acc[mf][nf], a[mf][0], a[mf][1], a[mf][2], a[mf][3],
                             b[nf][0], b[nf][1]);
        }
        __syncthreads();
    }

    // epilogue: S = sq_i + sq_j - 2G, softplus over strict upper triangle
    int g = lane >> 2, tg = lane & 3;
    float sqj[8][2];
    int jc[8];
    #pragma unroll
    for (int nf = 0; nf < 8; nf++) {
        int j0 = jBase + warpCol * 64 + nf * 8 + 2 * tg;
        jc[nf] = j0;
        sqj[nf][0] = g_sq[j0];
        sqj[nf][1] = g_sq[j0 + 1];
    }

    float lsum = 0.f;
    #pragma unroll
    for (int mf = 0; mf < 4; mf++) {
        int i0 = iBase + warpRow * 64 + mf * 16 + g;
        float sqi0 = g_sq[i0], sqi1 = g_sq[i0 + 8];
        #pragma unroll
        for (int nf = 0; nf < 8; nf++) {
            int j0 = jc[nf];
            float S;
            if (i0 < j0) {
                S = sqi0 + sqj[nf][0] - 2.f * acc[mf][nf][0];
                lsum += fmaxf(S, 0.f) + __logf(1.f + __expf(-fabsf(S)));
            }
            if (i0 < j0 + 1) {
                S = sqi0 + sqj[nf][1] - 2.f * acc[mf][nf][1];
                lsum += fmaxf(S, 0.f) + __logf(1.f + __expf(-fabsf(S)));
            }
            if (i0 + 8 < j0) {
                S = sqi1 + sqj[nf][0] - 2.f * acc[mf][nf][2];
                lsum += fmaxf(S, 0.f) + __logf(1.f + __expf(-fabsf(S)));
            }
            if (i0 + 8 < j0 + 1) {
                S = sqi1 + sqj[nf][1] - 2.f * acc[mf][nf][3];
                lsum += fmaxf(S, 0.f) + __logf(1.f + __expf(-fabsf(S)));
            }
        }
    }

    red[t] = lsum; __syncthreads();
    for (int off = 128; off > 0; off >>= 1) { if (t < off) red[t] += red[t + off]; __syncthreads(); }
    if (t == 0) atomicAdd(&g_pairsum, (double)red[0]);
}

// loss = (2*pairsum - sum_k (2 c_k P_k - 2 wss_k)) / (N(N-1))
__global__ void k_final(float* __restrict__ out) {
    __shared__ float red[NCLS];
    int t = threadIdx.x;
    float c = (float)g_counts[t];
    red[t] = 2.f * c * g_P[t] - 2.f * g_wss[t];
    __syncthreads();
    if (t == 0) {
        double ts = 0.0;
        for (int k = 0; k < NCLS; k++) ts += (double)red[k];
        double denom = (double)NPTS * (double)(NPTS - 1);
        out[0] = (float)((2.0 * g_pairsum - ts) / denom);
    }
}

// ------------------------------------------------------------------
extern "C" void kernel_launch(void* const* d_in, const int* in_sizes, int n_in,
                              void* d_out, int out_size) {
    const float* X   = (const float*)d_in[0];
    const int*   tgt = (const int*)d_in[1];
    float*       out = (float*)d_out;
    (void)in_sizes; (void)n_in; (void)out_size;

    cudaFuncSetAttribute(k_main, cudaFuncAttributeMaxDynamicSharedMemorySize, DSMEM_BYTES);

    k_zero<<<1, 128>>>();
    k_count<<<NPTS / 256, 256>>>(tgt);
    k_phase1<<<dim3(NDCH, RCH), 64>>>(X, tgt);
    k_reduce_w<<<DIMS, NCLS>>>();
    k_wss<<<NCLS, 256>>>();
    k_xwsq<<<NPTS, 256>>>(X, tgt);
    k_main<<<NTILES, 256, DSMEM_BYTES>>>();
    k_final<<<1, NCLS>>>(out);
}

// round 10
// speedup vs baseline: 5.1782x; 1.1810x over previous
#include <cuda_runtime.h>
#include <cuda_bf16.h>
#include <cstdint>

#define NPTS 4096
#define DIMS 1024
#define NCLS 64
#define EPSV 0.1f

#define RCH  64                 // row chunks for phase-1 partials
#define RPC  (NPTS / RCH)       // 64 rows per chunk
#define DCH  64                 // dims per phase-1 block
#define NDCH (DIMS / DCH)       // 16

// k_main tiling (bf16 mma.sync m16n8k16)
#define BM   256
#define BN   128
#define BK   64                 // bf16 elems per chunk = 128 B per row
#define NCH  (DIMS / BK)        // 16 chunks
#define NTILES 272              // triangle tiles: sum_{bi<16} (32 - 2*bi)
#define LSTRH 72                // smem row stride in halfs (144 B)
#define A_BYTES (BM * LSTRH * 2)   // 36864
#define B_BYTES (BN * LSTRH * 2)   // 18432
#define STGB  (A_BYTES + B_BYTES)  // 55296 B per stage
#define NSTG  3
#define DSMEM_BYTES (NSTG * STGB)  // 165888 B

// ---- static device scratch (no allocations allowed) ----
__device__ int      g_counts[NCLS];
__device__ float    g_spart[RCH][DIMS][NCLS];   // 16 MB partial class sums
__device__ float    g_Apart[RCH][DIMS];
__device__ float    g_Qpart[RCH][DIMS];
__device__ float    g_s[NCLS][DIMS];
__device__ float    g_w[DIMS];
__device__ unsigned short g_xh[(size_t)NPTS * DIMS];   // bf16(x)
__device__ unsigned short g_xwh[(size_t)NPTS * DIMS];  // bf16(w*x)
__device__ float    g_sq[NPTS];                 // sq_i = sum_d w_d x_id^2 (fp32 exact)
__device__ float    g_P[NCLS];
__device__ float    g_wss[NCLS];
__device__ double   g_pairsum;

// ---------------- helpers ----------------
__device__ __forceinline__ uint32_t smem_u32(const void* p) {
    uint32_t a;
    asm("{ .reg .u64 t; cvta.to.shared.u64 t, %1; cvt.u32.u64 %0, t; }" : "=r"(a) : "l"(p));
    return a;
}
__device__ __forceinline__ void cp16(uint32_t dst, const void* src) {
    asm volatile("cp.async.cg.shared.global [%0], [%1], 16;" :: "r"(dst), "l"(src) : "memory");
}
__device__ __forceinline__ void ldm_x4(uint32_t& r0, uint32_t& r1, uint32_t& r2, uint32_t& r3,
                                       uint32_t addr) {
    asm volatile("ldmatrix.sync.aligned.m8n8.x4.shared.b16 {%0,%1,%2,%3}, [%4];"
                 : "=r"(r0), "=r"(r1), "=r"(r2), "=r"(r3) : "r"(addr));
}
__device__ __forceinline__ void mma_bf16(float* c, uint32_t a0, uint32_t a1, uint32_t a2,
                                         uint32_t a3, uint32_t b0, uint32_t b1) {
    asm volatile("mma.sync.aligned.m16n8k16.row.col.f32.bf16.bf16.f32 "
                 "{%0,%1,%2,%3}, {%4,%5,%6,%7}, {%8,%9}, {%0,%1,%2,%3};"
                 : "+f"(c[0]), "+f"(c[1]), "+f"(c[2]), "+f"(c[3])
                 : "r"(a0), "r"(a1), "r"(a2), "r"(a3), "r"(b0), "r"(b1));
}

// ------------------------------------------------------------------
__global__ void k_zero() {
    int t = threadIdx.x;
    if (t < NCLS) { g_counts[t] = 0; g_P[t] = 0.f; }
    if (t == NCLS) g_pairsum = 0.0;
}

__global__ void k_count(const int* __restrict__ tgt) {
    int i = blockIdx.x * blockDim.x + threadIdx.x;
    if (i < NPTS) atomicAdd(&g_counts[tgt[i]], 1);
}

__global__ void k_phase1(const float* __restrict__ X, const int* __restrict__ tgt) {
    __shared__ float s_sh[NCLS * DCH];
    __shared__ float cnt_sh[NCLS];
    __shared__ int   tg_sh[RPC];
    int t  = threadIdx.x;                // 0..63
    int dc = blockIdx.x, rc = blockIdx.y;

    for (int i = t; i < NCLS * DCH; i += 64) s_sh[i] = 0.f;
    cnt_sh[t] = (float)g_counts[t];
    if (t < RPC) tg_sh[t] = tgt[rc * RPC + t];
    __syncthreads();

    const float* xp = X + (size_t)(rc * RPC) * DIMS + dc * DCH + t;
    float aacc = 0.f, qacc = 0.f;
    #pragma unroll 8
    for (int r = 0; r < RPC; r++) {
        float v = xp[(size_t)r * DIMS];
        int   k = tg_sh[r];
        s_sh[k * DCH + t] += v;
        float v2 = v * v;
        qacc += v2;
        aacc = fmaf(cnt_sh[k], v2, aacc);
    }
    __syncthreads();

    int d = dc * DCH + t;
    #pragma unroll
    for (int k4 = 0; k4 < NCLS; k4 += 4) {
        float4 v = make_float4(s_sh[(k4 + 0) * DCH + t], s_sh[(k4 + 1) * DCH + t],
                               s_sh[(k4 + 2) * DCH + t], s_sh[(k4 + 3) * DCH + t]);
        *(float4*)&g_spart[rc][d][k4] = v;
    }
    g_Apart[rc][d] = aacc;
    g_Qpart[rc][d] = qacc;
}

__global__ void k_reduce_w() {
    int d = blockIdx.x, k = threadIdx.x;   // k = class id AND rc id (both 64)
    float s = 0.f;
    #pragma unroll 8
    for (int rc = 0; rc < RCH; rc++) s += g_spart[rc][d][k];
    g_s[k][d] = s;
    float c = (float)g_counts[k];

    __shared__ float sh1[NCLS], sh2[NCLS], sh3[NCLS], sh4[NCLS], sh5[NCLS];
    sh1[k] = s * s; sh2[k] = s; sh3[k] = c * c;
    sh4[k] = g_Apart[k][d];        // thread k doubles as rc=k
    sh5[k] = g_Qpart[k][d];
    __syncthreads();
    for (int off = 32; off > 0; off >>= 1) {
        if (k < off) {
            sh1[k] += sh1[k + off]; sh2[k] += sh2[k + off]; sh3[k] += sh3[k + off];
            sh4[k] += sh4[k + off]; sh5[k] += sh5[k + off];
        }
        __syncthreads();
    }

    if (k == 0) {
        float ssum2 = sh1[0], stot = sh2[0], sumc2 = sh3[0];
        float a = sh4[0], q = sh5[0];
        float cntpos = sumc2 - (float)NPTS;
        float cntneg = (float)NPTS * (float)NPTS - sumc2;
        float sum_pos = 2.f * a - 2.f * ssum2;
        float sum_neg = 2.f * (float)NPTS * q - 2.f * a - 2.f * stot * stot + 2.f * ssum2;
        g_w[d] = cntneg / (sum_neg + EPSV) - cntpos / (sum_pos + EPSV);
    }
}

__global__ void k_wss() {
    int k = blockIdx.x, t = threadIdx.x;
    float p = 0.f;
    for (int d = t; d < DIMS; d += 256) { float s = g_s[k][d]; p = fmaf(g_w[d] * s, s, p); }
    __shared__ float red[256];
    red[t] = p; __syncthreads();
    for (int off = 128; off > 0; off >>= 1) { if (t < off) red[t] += red[t + off]; __syncthreads(); }
    if (t == 0) g_wss[k] = red[0];
}

// xh = bf16(x), xwh = bf16(w*x), sq_i = sum w x^2 (fp32), P_k += sq_i
__global__ void k_xwsq(const float* __restrict__ X, const int* __restrict__ tgt) {
    int i = blockIdx.x, t = threadIdx.x;   // 256 threads, 4 dims each
    const float4* xr = (const float4*)(X + (size_t)i * DIMS);
    const float4* wr = (const float4*)g_w;
    float4 x4 = xr[t], w4 = wr[t], o;
    o.x = x4.x * w4.x; o.y = x4.y * w4.y; o.z = x4.z * w4.z; o.w = x4.w * w4.w;
    float acc = x4.x * o.x + x4.y * o.y + x4.z * o.z + x4.w * o.w;

    __nv_bfloat162 hx0 = __floats2bfloat162_rn(x4.x, x4.y);
    __nv_bfloat162 hx1 = __floats2bfloat162_rn(x4.z, x4.w);
    __nv_bfloat162 ho0 = __floats2bfloat162_rn(o.x, o.y);
    __nv_bfloat162 ho1 = __floats2bfloat162_rn(o.z, o.w);
    uint2* dxh  = (uint2*)(g_xh  + (size_t)i * DIMS);
    uint2* dxwh = (uint2*)(g_xwh + (size_t)i * DIMS);
    uint2 px, po;
    px.x = *(uint32_t*)&hx0; px.y = *(uint32_t*)&hx1;
    po.x = *(uint32_t*)&ho0; po.y = *(uint32_t*)&ho1;
    dxh[t] = px; dxwh[t] = po;

    __shared__ float red[256];
    red[t] = acc; __syncthreads();
    for (int off = 128; off > 0; off >>= 1) { if (t < off) red[t] += red[t + off]; __syncthreads(); }
    if (t == 0) { g_sq[i] = red[0]; atomicAdd(&g_P[tgt[i]], red[0]); }
}

// ------------------------------------------------------------------
// bf16 mma.sync fused Gram + softplus. 256x128 tile, BK=64, 3-stage cp.async,
// ldmatrix.x4 fragments, 8 warps (4m x 2n) each 64x64.
__device__ __forceinline__ void load_stage(uint32_t sA, uint32_t sB,
                                           const unsigned short* Ag,
                                           const unsigned short* Bg,
                                           int kt, int t) {
    int seg = t & 7;               // 16B segment within 128B row
    int r0  = t >> 3;              // 32 rows per pass
    #pragma unroll
    for (int p = 0; p < 8; p++) {  // A: 256 rows
        int row = r0 + 32 * p;
        cp16(sA + row * 144u + seg * 16u, Ag + (size_t)row * DIMS + kt + seg * 8);
    }
    #pragma unroll
    for (int p = 0; p < 4; p++) {  // B: 128 rows
        int row = r0 + 32 * p;
        cp16(sB + row * 144u + seg * 16u, Bg + (size_t)row * DIMS + kt + seg * 8);
    }
    asm volatile("cp.async.commit_group;" ::: "memory");
}

__global__ void __launch_bounds__(256) k_main() {
    // map linear block id -> (bi, bj) on the triangle bj >= 2*bi
    int L = blockIdx.x, bi = 0, cnt = 32;
    while (L >= cnt) { L -= cnt; bi++; cnt -= 2; }
    int bj = 2 * bi + L;
    int iBase = bi * BM, jBase = bj * BN;

    extern __shared__ char dsmem[];
    __shared__ float red[256];
    __shared__ float sqi_sh[BM];
    __shared__ float sqj_sh[BN];

    int t = threadIdx.x;
    int lane = t & 31, w = t >> 5;
    int warpRow = w & 3, warpCol = w >> 2;    // 4 x 2 warps
    uint32_t sbase = smem_u32(dsmem);

    const unsigned short* Ag = g_xh  + (size_t)iBase * DIMS;
    const unsigned short* Bg = g_xwh + (size_t)jBase * DIMS;

    // prefetch sq rows/cols for the epilogue
    sqi_sh[t] = g_sq[iBase + t];
    if (t < BN) sqj_sh[t] = g_sq[jBase + t];

    float acc[4][8][4];
    #pragma unroll
    for (int mf = 0; mf < 4; mf++)
        #pragma unroll
        for (int nf = 0; nf < 8; nf++)
            #pragma unroll
            for (int q = 0; q < 4; q++) acc[mf][nf][q] = 0.f;

    // prologue: chunks 0 and 1 into stages 0 and 1
    load_stage(sbase,        sbase + A_BYTES,        Ag, Bg, 0,  t);
    load_stage(sbase + STGB, sbase + STGB + A_BYTES, Ag, Bg, BK, t);

    // precomputed fragment address components
    uint32_t aRow = (uint32_t)(warpRow * 64 + (lane & 15));
    uint32_t aKof = (uint32_t)((lane >> 4) * 16);
    int grp = lane >> 3;
    uint32_t bRowB = (uint32_t)(warpCol * 64 + ((grp >> 1) << 3) + (lane & 7));
    uint32_t bKof = (uint32_t)((grp & 1) * 16);

    for (int c = 0; c < NCH; c++) {
        uint32_t sA = sbase + (uint32_t)(c % NSTG) * STGB;
        uint32_t sB = sA + A_BYTES;
        if (c + 2 < NCH) asm volatile("cp.async.wait_group 1;" ::: "memory");
        else             asm volatile("cp.async.wait_group 0;" ::: "memory");
        __syncthreads();

        if (c + 2 < NCH)
            load_stage(sbase + (uint32_t)((c + 2) % NSTG) * STGB,
                       sbase + (uint32_t)((c + 2) % NSTG) * STGB + A_BYTES,
                       Ag, Bg, (c + 2) * BK, t);

        #pragma unroll
        for (int ks = 0; ks < 4; ks++) {
            uint32_t a[4][4], b[8][2];
            #pragma unroll
            for (int nfp = 0; nfp < 4; nfp++) {
                uint32_t addr = sB + (bRowB + nfp * 16) * 144u + ks * 32u + bKof;
                ldm_x4(b[2 * nfp][0], b[2 * nfp][1], b[2 * nfp + 1][0], b[2 * nfp + 1][1], addr);
            }
            #pragma unroll
            for (int mf = 0; mf < 4; mf++) {
                uint32_t addr = sA + (aRow + mf * 16) * 144u + ks * 32u + aKof;
                ldm_x4(a[mf][0], a[mf][1], a[mf][2], a[mf][3], addr);
            }
            #pragma unroll
            for (int mf = 0; mf < 4; mf++)
                #pragma unroll
                for (int nf = 0; nf < 8; nf++)
                    mma_bf16(acc[mf][nf], a[mf][0], a[mf][1], a[mf][2], a[mf][3],
                             b[nf][0], b[nf][1]);
        }
        __syncthreads();
    }

    // epilogue: S = sq_i + sq_j - 2G, softplus over strict upper triangle
    int g = lane >> 2, tg = lane & 3;
    float sqj[8][2];
    int jc[8];
    #pragma unroll
    for (int nf = 0; nf < 8; nf++) {
        int jl = warpCol * 64 + nf * 8 + 2 * tg;
        jc[nf] = jBase + jl;
        sqj[nf][0] = sqj_sh[jl];
        sqj[nf][1] = sqj_sh[jl + 1];
    }

    float lsum = 0.f;
    #pragma unroll
    for (int mf = 0; mf < 4; mf++) {
        int il = warpRow * 64 + mf * 16 + g;
        int i0 = iBase + il;
        float sqi0 = sqi_sh[il], sqi1 = sqi_sh[il + 8];
        #pragma unroll
        for (int nf = 0; nf < 8; nf++) {
            int j0 = jc[nf];
            float S;
            if (i0 < j0) {
                S = sqi0 + sqj[nf][0] - 2.f * acc[mf][nf][0];
                lsum += fmaxf(S, 0.f) + __logf(1.f + __expf(-fabsf(S)));
            }
            if (i0 < j0 + 1) {
                S = sqi0 + sqj[nf][1] - 2.f * acc[mf][nf][1];
                lsum += fmaxf(S, 0.f) + __logf(1.f + __expf(-fabsf(S)));
            }
            if (i0 + 8 < j0) {
                S = sqi1 + sqj[nf][0] - 2.f * acc[mf][nf][2];
                lsum += fmaxf(S, 0.f) + __logf(1.f + __expf(-fabsf(S)));
            }
            if (i0 + 8 < j0 + 1) {
                S = sqi1 + sqj[nf][1] - 2.f * acc[mf][nf][3];
                lsum += fmaxf(S, 0.f) + __logf(1.f + __expf(-fabsf(S)));
            }
        }
    }

    red[t] = lsum; __syncthreads();
    for (int off = 128; off > 0; off >>= 1) { if (t < off) red[t] += red[t + off]; __syncthreads(); }
    if (t == 0) atomicAdd(&g_pairsum, (double)red[0]);
}

// loss = (2*pairsum - sum_k (2 c_k P_k - 2 wss_k)) / (N(N-1))
__global__ void k_final(float* __restrict__ out) {
    __shared__ float red[NCLS];
    int t = threadIdx.x;
    float c = (float)g_counts[t];
    red[t] = 2.f * c * g_P[t] - 2.f * g_wss[t];
    __syncthreads();
    if (t == 0) {
        double ts = 0.0;
        for (int k = 0; k < NCLS; k++) ts += (double)red[k];
        double denom = (double)NPTS * (double)(NPTS - 1);
        out[0] = (float)((2.0 * g_pairsum - ts) / denom);
    }
}

// ------------------------------------------------------------------
extern "C" void kernel_launch(void* const* d_in, const int* in_sizes, int n_in,
                              void* d_out, int out_size) {
    const float* X   = (const float*)d_in[0];
    const int*   tgt = (const int*)d_in[1];
    float*       out = (float*)d_out;
    (void)in_sizes; (void)n_in; (void)out_size;

    cudaFuncSetAttribute(k_main, cudaFuncAttributeMaxDynamicSharedMemorySize, DSMEM_BYTES);

    k_zero<<<1, 128>>>();
    k_count<<<NPTS / 256, 256>>>(tgt);
    k_phase1<<<dim3(NDCH, RCH), 64>>>(X, tgt);
    k_reduce_w<<<DIMS, NCLS>>>();
    k_wss<<<NCLS, 256>>>();
    k_xwsq<<<NPTS, 256>>>(X, tgt);
    k_main<<<NTILES, 256, DSMEM_BYTES>>>();
    k_final<<<1, NCLS>>>(out);
}